// round 5
// baseline (speedup 1.0000x reference)
#include <cuda_runtime.h>
#include <cstdint>

#define T_DIM 4096
#define B_DIM 32
#define H_DIM 256
#define L_DIM 512
#define K_DIM 32
#define T_BLK 128

// Scratch (allocation-free contract: __device__ globals)
__device__ __align__(16) float g_kern[B_DIM * H_DIM * K_DIM];   // [b][h*K+k] fp32
__device__ __align__(16) float g_glob[B_DIM * H_DIM];           // (B,H)
__device__ __align__(16) float g_exp[T_DIM * B_DIM];            // exp(score+mask)
__device__ __align__(16) float g_part[(T_DIM / T_BLK) * B_DIM]; // partial exp sums

// ---- helpers ----
__device__ __forceinline__ float tanh_ap(float x) {
    float y; asm("tanh.approx.f32 %0, %1;" : "=f"(y) : "f"(x)); return y;
}
__device__ __forceinline__ unsigned cvt_bf2(float lo, float hi) {
    unsigned d; asm("cvt.rn.bf16x2.f32 %0, %1, %2;" : "=r"(d) : "f"(hi), "f"(lo)); return d;
}
// tf32 cvt: destination is a .b32 register
__device__ __forceinline__ float cvt_tf32(float x) {
    uint32_t y; asm("cvt.rna.tf32.f32 %0, %1;" : "=r"(y) : "f"(x));
    return __uint_as_float(y);
}
__device__ __forceinline__ uint32_t smem_u32(const void* p) {
    return (uint32_t)__cvta_generic_to_shared(p);
}
__device__ __forceinline__ void ldsm_x4(unsigned r[4], uint32_t addr) {
    asm volatile("ldmatrix.sync.aligned.m8n8.x4.shared.b16 {%0,%1,%2,%3}, [%4];"
        : "=r"(r[0]), "=r"(r[1]), "=r"(r[2]), "=r"(r[3]) : "r"(addr));
}
__device__ __forceinline__ void ldsm_x2(unsigned& r0, unsigned& r1, uint32_t addr) {
    asm volatile("ldmatrix.sync.aligned.m8n8.x2.shared.b16 {%0,%1}, [%2];"
        : "=r"(r0), "=r"(r1) : "r"(addr));
}
__device__ __forceinline__ void mma_bf16(float c[4], const unsigned a[4], const unsigned b[2]) {
    asm volatile("mma.sync.aligned.m16n8k16.row.col.f32.bf16.bf16.f32 "
        "{%0,%1,%2,%3}, {%4,%5,%6,%7}, {%8,%9}, {%0,%1,%2,%3};"
        : "+f"(c[0]), "+f"(c[1]), "+f"(c[2]), "+f"(c[3])
        : "r"(a[0]), "r"(a[1]), "r"(a[2]), "r"(a[3]), "r"(b[0]), "r"(b[1]));
}
__device__ __forceinline__ void mma_tf32(float c[4],
    float a0, float a1, float a2, float a3, float b0, float b1) {
    asm volatile("mma.sync.aligned.m16n8k8.row.col.f32.tf32.tf32.f32 "
        "{%0,%1,%2,%3}, {%4,%5,%6,%7}, {%8,%9}, {%0,%1,%2,%3};"
        : "+f"(c[0]), "+f"(c[1]), "+f"(c[2]), "+f"(c[3])
        : "r"(__float_as_uint(a0)), "r"(__float_as_uint(a1)),
          "r"(__float_as_uint(a2)), "r"(__float_as_uint(a3)),
          "r"(__float_as_uint(b0)), "r"(__float_as_uint(b1)));
}

// ============================================================================
// Kernel A: tf32 tensor-core GEMM  out[b,row] = dot(lm[b,:], W[row,:]) + bias
// M = 8192 Wk rows ++ 256 Wg rows, N = 32 (b), K = 512.
// Block = 64 rows x 32 b, 128 threads (4 warps); warp = 16 rows (1 m-tile)
// x 32 b (4 n-tiles). K staged in 32-wide chunks; 132 blocks = 1 wave.
// ============================================================================
#define GB_ROWS 64
#define WP 36    // W tile pitch (floats)
#define BP 40    // lm tile pitch

__global__ void __launch_bounds__(128) gemm_tc_kernel(
    const float* __restrict__ Wk, const float* __restrict__ bk,
    const float* __restrict__ Wg, const float* __restrict__ bg,
    const float* __restrict__ lm)
{
    const int tid  = threadIdx.x;
    const int warp = tid >> 5;
    const int lane = tid & 31;
    const int g    = lane >> 2;   // 0..7
    const int t4   = lane & 3;    // 0..3

    const bool is_k = (blockIdx.x < (K_DIM * H_DIM) / GB_ROWS);   // first 128 blocks
    const float* W    = is_k ? Wk : Wg;
    const float* bias = is_k ? bk : bg;
    const int rowbase = (is_k ? blockIdx.x : (blockIdx.x - (K_DIM * H_DIM) / GB_ROWS)) * GB_ROWS;

    __shared__ __align__(16) float Wt[GB_ROWS * WP];   // 64 rows x 32 k
    __shared__ __align__(16) float Bt[32 * BP];        // 32 k x 32 b

    float c[4][4];
    #pragma unroll
    for (int nt = 0; nt < 4; nt++)
        #pragma unroll
        for (int j = 0; j < 4; j++) c[nt][j] = 0.f;

    for (int kk = 0; kk < L_DIM; kk += 32) {
        // stage W tile: 64 rows x 32 k = 512 float4 slots
        #pragma unroll
        for (int i = 0; i < 4; i++) {
            int s = tid + 128 * i;
            int row = s >> 3, c4 = (s & 7) * 4;
            float4 v = *reinterpret_cast<const float4*>(
                W + (size_t)(rowbase + row) * L_DIM + kk + c4);
            float* dst = &Wt[row * WP + c4];
            dst[0] = cvt_tf32(v.x); dst[1] = cvt_tf32(v.y);
            dst[2] = cvt_tf32(v.z); dst[3] = cvt_tf32(v.w);
        }
        // stage lm tile: Bt[k][b], coalesced over k
        #pragma unroll
        for (int i = 0; i < 8; i++) {
            int s = tid + 128 * i;
            int bb = s >> 5, k = s & 31;
            Bt[k * BP + bb] = cvt_tf32(lm[(size_t)bb * L_DIM + kk + k]);
        }
        __syncthreads();

        #pragma unroll
        for (int ks = 0; ks < 4; ks++) {
            const float* ar = &Wt[(warp * 16 + g) * WP + ks * 8 + t4];
            float a0 = ar[0], a1 = ar[8 * WP], a2 = ar[4], a3 = ar[8 * WP + 4];
            #pragma unroll
            for (int nt = 0; nt < 4; nt++) {
                float b0 = Bt[(ks * 8 + t4) * BP + nt * 8 + g];
                float b1 = Bt[(ks * 8 + 4 + t4) * BP + nt * 8 + g];
                mma_tf32(c[nt], a0, a1, a2, a3, b0, b1);
            }
        }
        __syncthreads();
    }

    // epilogue: c[nt][0,1] -> (row0, b0/b0+1), c[nt][2,3] -> (row0+8, ...)
    const int row0 = rowbase + warp * 16 + g;
    const float bv0 = bias[row0];
    const float bv1 = bias[row0 + 8];
    #pragma unroll
    for (int nt = 0; nt < 4; nt++) {
        int bb = nt * 8 + t4 * 2;
        if (is_k) {
            float* o0 = g_kern + (size_t)bb * (H_DIM * K_DIM);
            o0[row0]                       = c[nt][0] + bv0;
            o0[row0 + H_DIM * K_DIM]       = c[nt][1] + bv0;   // bb+1
            o0[row0 + 8]                   = c[nt][2] + bv1;
            o0[row0 + 8 + H_DIM * K_DIM]   = c[nt][3] + bv1;
        } else {
            float* o0 = g_glob + (size_t)bb * H_DIM;
            o0[row0]             = c[nt][0] + bv0;
            o0[row0 + H_DIM]     = c[nt][1] + bv0;
            o0[row0 + 8]         = c[nt][2] + bv1;
            o0[row0 + 8 + H_DIM] = c[nt][3] + bv1;
        }
    }
}

// ============================================================================
// Kernel B: tensor-core conv + enc + global -> tanh -> Ws -> exp
// Block: (t-block of 128, b). 128 threads = 4 warps; warp owns 64 h.
// enc loads for the whole m-iteration are prefetched BEFORE the MMAs.
// ============================================================================
__global__ void __launch_bounds__(128) score_kernel(
    const float* __restrict__ enc,   // (T,B,H)
    const float* __restrict__ prev,  // (T,B)
    const float* __restrict__ mask,  // (T,B)
    const float* __restrict__ Ws,    // (H)
    const float* __restrict__ bsp)   // (1)
{
    const int b    = blockIdx.y;
    const int t0   = blockIdx.x * T_BLK;
    const int tid  = threadIdx.x;
    const int wid  = tid >> 5;
    const int lane = tid & 31;
    const int gid  = lane >> 2;   // 0..7
    const int tig  = lane & 3;    // 0..3

    __shared__ float win_s[160];                       // prev_pad window
    __shared__ __align__(16) unsigned A_sm[128 * 20];  // bf16x2, pitch 20 u32
    __shared__ __align__(16) unsigned B_sm[256 * 20];
    __shared__ float part[T_BLK][4];
    __shared__ float red4[4];

    // ---- fill prev window + B (kern -> bf16) ----
    for (int i = tid; i < 160; i += 128) {
        int tg = t0 + i - (K_DIM - 1);
        win_s[i] = (tg >= 0 && tg < T_DIM) ? prev[(size_t)tg * B_DIM + b] : 0.f;
    }
    {
        const float2* kp = reinterpret_cast<const float2*>(g_kern + (size_t)b * H_DIM * K_DIM);
        #pragma unroll
        for (int i = tid; i < (H_DIM * K_DIM) / 2; i += 128) {
            float2 v = kp[i];
            int h = i >> 4, k2 = i & 15;
            B_sm[h * 20 + k2] = cvt_bf2(v.x, v.y);
        }
    }
    __syncthreads();

    // ---- fill A (Hankel windows, bf16) ----
    {
        int r = tid;
        #pragma unroll
        for (int k2 = 0; k2 < 16; k2++)
            A_sm[r * 20 + k2] = cvt_bf2(win_s[r + 2 * k2], win_s[r + 2 * k2 + 1]);
    }

    // ---- B fragments (resident) + per-lane epilogue constants ----
    const int hw0 = wid * 64;
    unsigned Bf[8][2][2];
    {
        uint32_t bbase = smem_u32(B_sm);
        #pragma unroll
        for (int j = 0; j < 8; j++)
            #pragma unroll
            for (int kt = 0; kt < 2; kt++) {
                uint32_t addr = bbase + (uint32_t)(hw0 + j * 8 + (lane & 7)) * 80
                              + kt * 32 + ((lane >> 3) & 1) * 16;
                ldsm_x2(Bf[j][kt][0], Bf[j][kt][1], addr);
            }
    }
    float2 gv2[8], ws2[8];
    #pragma unroll
    for (int j = 0; j < 8; j++) {
        int h0 = hw0 + j * 8 + 2 * tig;
        gv2[j] = *reinterpret_cast<const float2*>(g_glob + (size_t)b * H_DIM + h0);
        ws2[j] = *reinterpret_cast<const float2*>(Ws + h0);
    }
    __syncthreads();

    const uint32_t abase = smem_u32(A_sm);
    const uint32_t a_off = (uint32_t)(lane & 15) * 80 + (uint32_t)(lane >> 4) * 16;

    #pragma unroll 1
    for (int m = 0; m < 8; m++) {
        unsigned a0[4], a1[4];
        ldsm_x4(a0, abase + (uint32_t)m * 16 * 80 + a_off);        // k 0..15
        ldsm_x4(a1, abase + (uint32_t)m * 16 * 80 + a_off + 32);   // k 16..31

        const int ta = t0 + m * 16 + gid;
        const float* e_row0 = enc + ((size_t)ta * B_DIM + b) * H_DIM;
        const float* e_row1 = e_row0 + (size_t)8 * B_DIM * H_DIM;

        // prefetch all enc values for this m BEFORE the MMAs
        float2 ev0[8], ev1[8];
        #pragma unroll
        for (int j = 0; j < 8; j++) {
            int h0 = hw0 + j * 8 + 2 * tig;
            ev0[j] = *reinterpret_cast<const float2*>(e_row0 + h0);
            ev1[j] = *reinterpret_cast<const float2*>(e_row1 + h0);
        }

        float sum0 = 0.f, sum1 = 0.f;
        #pragma unroll
        for (int jh = 0; jh < 2; jh++) {
            float c[4][4];
            #pragma unroll
            for (int j4 = 0; j4 < 4; j4++) {
                c[j4][0] = c[j4][1] = c[j4][2] = c[j4][3] = 0.f;
                mma_bf16(c[j4], a0, Bf[jh * 4 + j4][0]);
                mma_bf16(c[j4], a1, Bf[jh * 4 + j4][1]);
            }
            #pragma unroll
            for (int j4 = 0; j4 < 4; j4++) {
                int j = jh * 4 + j4;
                sum0 += ws2[j].x * tanh_ap(c[j4][0] + ev0[j].x + gv2[j].x)
                      + ws2[j].y * tanh_ap(c[j4][1] + ev0[j].y + gv2[j].y);
                sum1 += ws2[j].x * tanh_ap(c[j4][2] + ev1[j].x + gv2[j].x)
                      + ws2[j].y * tanh_ap(c[j4][3] + ev1[j].y + gv2[j].y);
            }
        }
        // reduce over tig (4 lanes sharing a row)
        sum0 += __shfl_xor_sync(0xFFFFFFFFu, sum0, 1);
        sum0 += __shfl_xor_sync(0xFFFFFFFFu, sum0, 2);
        sum1 += __shfl_xor_sync(0xFFFFFFFFu, sum1, 1);
        sum1 += __shfl_xor_sync(0xFFFFFFFFu, sum1, 2);
        if (tig == 0) {
            part[m * 16 + gid][wid]     = sum0;
            part[m * 16 + gid + 8][wid] = sum1;
        }
    }
    __syncthreads();

    // finalize: one t per thread -> exp -> block sum
    const int t = t0 + tid;
    float s = part[tid][0] + part[tid][1] + part[tid][2] + part[tid][3] + bsp[0];
    float e = __expf(s + mask[(size_t)t * B_DIM + b]);
    g_exp[(size_t)t * B_DIM + b] = e;

    float v = e;
    v += __shfl_xor_sync(0xFFFFFFFFu, v, 16);
    v += __shfl_xor_sync(0xFFFFFFFFu, v, 8);
    v += __shfl_xor_sync(0xFFFFFFFFu, v, 4);
    v += __shfl_xor_sync(0xFFFFFFFFu, v, 2);
    v += __shfl_xor_sync(0xFFFFFFFFu, v, 1);
    if (lane == 0) red4[wid] = v;
    __syncthreads();
    if (tid == 0)
        g_part[(size_t)blockIdx.x * B_DIM + b] = red4[0] + red4[1] + red4[2] + red4[3];
}

// ============================================================================
// Kernel C: normalize  out[t,b] = g_exp[t,b] / sum_b
// ============================================================================
__global__ void __launch_bounds__(128) norm_kernel(float* __restrict__ out)
{
    __shared__ float inv_s;
    const int b = blockIdx.y;
    const int tid = threadIdx.x;

    if (tid < 32) {
        float v = g_part[(size_t)tid * B_DIM + b];
        v += __shfl_xor_sync(0xFFFFFFFFu, v, 16);
        v += __shfl_xor_sync(0xFFFFFFFFu, v, 8);
        v += __shfl_xor_sync(0xFFFFFFFFu, v, 4);
        v += __shfl_xor_sync(0xFFFFFFFFu, v, 2);
        v += __shfl_xor_sync(0xFFFFFFFFu, v, 1);
        if (tid == 0) inv_s = 1.0f / v;
    }
    __syncthreads();

    int t = blockIdx.x * 128 + tid;
    out[(size_t)t * B_DIM + b] = g_exp[(size_t)t * B_DIM + b] * inv_s;
}

// ============================================================================
extern "C" void kernel_launch(void* const* d_in, const int* in_sizes, int n_in,
                              void* d_out, int out_size)
{
    const float* enc  = (const float*)d_in[0];
    const float* mask = (const float*)d_in[1];
    const float* lm   = (const float*)d_in[2];
    const float* prev = (const float*)d_in[3];
    const float* Wk   = (const float*)d_in[4];
    const float* bk   = (const float*)d_in[5];
    const float* Wg   = (const float*)d_in[6];
    const float* bg   = (const float*)d_in[7];
    const float* Ws   = (const float*)d_in[8];
    const float* bs   = (const float*)d_in[9];
    float* out = (float*)d_out;

    // Wk (128 blocks) + Wg (4 blocks), tf32 tensor cores
    gemm_tc_kernel<<<(K_DIM * H_DIM) / GB_ROWS + H_DIM / GB_ROWS, 128>>>(Wk, bk, Wg, bg, lm);
    // tensor-core conv + tanh + score + exp + partial sums
    score_kernel<<<dim3(T_DIM / T_BLK, B_DIM), 128>>>(enc, prev, mask, Ws, bs);
    // normalize
    norm_kernel<<<dim3(T_DIM / 128, B_DIM), 128>>>(out);
}

// round 6
// speedup vs baseline: 1.7659x; 1.7659x over previous
#include <cuda_runtime.h>
#include <cstdint>

#define T_DIM 4096
#define B_DIM 32
#define H_DIM 256
#define L_DIM 512
#define K_DIM 32
#define T_BLK 128

// Scratch (allocation-free contract: __device__ globals)
__device__ __align__(16) float g_kern[B_DIM * H_DIM * K_DIM];   // [b][h*K+k] fp32
__device__ __align__(16) float g_glob[B_DIM * H_DIM];           // (B,H)
__device__ __align__(16) float g_exp[T_DIM * B_DIM];            // exp(score+mask)
__device__ __align__(16) float g_part[(T_DIM / T_BLK) * B_DIM]; // partial exp sums

// ---- helpers ----
__device__ __forceinline__ float tanh_ap(float x) {
    float y; asm("tanh.approx.f32 %0, %1;" : "=f"(y) : "f"(x)); return y;
}
__device__ __forceinline__ unsigned cvt_bf2(float lo, float hi) {
    unsigned d; asm("cvt.rn.bf16x2.f32 %0, %1, %2;" : "=r"(d) : "f"(hi), "f"(lo)); return d;
}
__device__ __forceinline__ uint32_t smem_u32(const void* p) {
    return (uint32_t)__cvta_generic_to_shared(p);
}
__device__ __forceinline__ void cp_async16(uint32_t dst, const void* src) {
    asm volatile("cp.async.cg.shared.global [%0], [%1], 16;" :: "r"(dst), "l"(src));
}
__device__ __forceinline__ void cp_commit() {
    asm volatile("cp.async.commit_group;");
}
__device__ __forceinline__ void ldsm_x4(unsigned r[4], uint32_t addr) {
    asm volatile("ldmatrix.sync.aligned.m8n8.x4.shared.b16 {%0,%1,%2,%3}, [%4];"
        : "=r"(r[0]), "=r"(r[1]), "=r"(r[2]), "=r"(r[3]) : "r"(addr));
}
__device__ __forceinline__ void ldsm_x2(unsigned& r0, unsigned& r1, uint32_t addr) {
    asm volatile("ldmatrix.sync.aligned.m8n8.x2.shared.b16 {%0,%1}, [%2];"
        : "=r"(r0), "=r"(r1) : "r"(addr));
}
__device__ __forceinline__ void mma_bf16(float c[4], const unsigned a[4], const unsigned b[2]) {
    asm volatile("mma.sync.aligned.m16n8k16.row.col.f32.bf16.bf16.f32 "
        "{%0,%1,%2,%3}, {%4,%5,%6,%7}, {%8,%9}, {%0,%1,%2,%3};"
        : "+f"(c[0]), "+f"(c[1]), "+f"(c[2]), "+f"(c[3])
        : "r"(a[0]), "r"(a[1]), "r"(a[2]), "r"(a[3]), "r"(b[0]), "r"(b[1]));
}
// raw fp32 operands (hardware truncates to tf32 — cutlass fast path)
__device__ __forceinline__ void mma_tf32(float c[4],
    float a0, float a1, float a2, float a3, float b0, float b1) {
    asm volatile("mma.sync.aligned.m16n8k8.row.col.f32.tf32.tf32.f32 "
        "{%0,%1,%2,%3}, {%4,%5,%6,%7}, {%8,%9}, {%0,%1,%2,%3};"
        : "+f"(c[0]), "+f"(c[1]), "+f"(c[2]), "+f"(c[3])
        : "r"(__float_as_uint(a0)), "r"(__float_as_uint(a1)),
          "r"(__float_as_uint(a2)), "r"(__float_as_uint(a3)),
          "r"(__float_as_uint(b0)), "r"(__float_as_uint(b1)));
}

// ============================================================================
// Kernel A: tf32 MMA GEMM with cp.async 4-stage pipeline.
// out[b,row] = dot(lm[b,:], W[row,:]) + bias[row]
// M = 8192 Wk rows ++ 256 Wg rows, N = 32 (b), K = 512.
// Block: 256 threads (8 warps), tile 64 rows x 32 b. warp = m-tile (16 rows)
// x n-half (16 b). lm staged once ([b][k], pitch 516); W streamed in 32-k
// chunks (pitch 36). Both fragment LDS patterns are 32-bank conflict-free.
// ============================================================================
#define GB_ROWS 64
#define WPITCH  36
#define BPITCH  516
#define NSTAGE  4
#define NCHUNK  (L_DIM / 32)          // 16
#define GEMM_SMEM ((B_DIM * BPITCH + NSTAGE * GB_ROWS * WPITCH) * 4)

__global__ void __launch_bounds__(256) gemm_tc_kernel(
    const float* __restrict__ Wk, const float* __restrict__ bk,
    const float* __restrict__ Wg, const float* __restrict__ bg,
    const float* __restrict__ lm)
{
    extern __shared__ float smem[];
    float* Bt  = smem;                       // [32][516]
    float* Wst = smem + B_DIM * BPITCH;      // [4][64][36]

    const int tid  = threadIdx.x;
    const int warp = tid >> 5;
    const int lane = tid & 31;
    const int g    = lane >> 2;   // 0..7
    const int t4   = lane & 3;    // 0..3
    const int mt   = warp >> 1;   // m-tile 0..3
    const int nh   = warp & 1;    // n-half 0..1

    const bool is_k = (blockIdx.x < (K_DIM * H_DIM) / GB_ROWS);   // first 128 blocks
    const float* W    = is_k ? Wk : Wg;
    const float* bias = is_k ? bk : bg;
    const int rowbase = (is_k ? blockIdx.x : (blockIdx.x - (K_DIM * H_DIM) / GB_ROWS)) * GB_ROWS;

    const uint32_t bt_base = smem_u32(Bt);
    const uint32_t ws_base = smem_u32(Wst);

    // --- group 0: lm -> Bt[b][k] (4096 float4 slots) ---
    #pragma unroll
    for (int i = 0; i < 16; i++) {
        int s = tid + 256 * i;
        int bb = s >> 7, k4 = (s & 127) * 4;
        cp_async16(bt_base + (uint32_t)(bb * BPITCH + k4) * 4,
                   lm + (size_t)bb * L_DIM + k4);
    }
    cp_commit();

    // --- prologue: W chunks 0..2 ---
    #pragma unroll
    for (int st = 0; st < NSTAGE - 1; st++) {
        #pragma unroll
        for (int i = 0; i < 2; i++) {
            int s = tid + 256 * i;                 // 512 float4 slots
            int row = s >> 3, c4 = (s & 7) * 4;
            cp_async16(ws_base + (uint32_t)(st * GB_ROWS * WPITCH + row * WPITCH + c4) * 4,
                       W + (size_t)(rowbase + row) * L_DIM + st * 32 + c4);
        }
        cp_commit();
    }

    float c[2][4];
    #pragma unroll
    for (int nt = 0; nt < 2; nt++)
        #pragma unroll
        for (int j = 0; j < 4; j++) c[nt][j] = 0.f;

    #pragma unroll 1
    for (int ch = 0; ch < NCHUNK; ch++) {
        asm volatile("cp.async.wait_group 2;");
        __syncthreads();

        const float* ws = Wst + (ch & 3) * GB_ROWS * WPITCH;
        const int kk = ch * 32;
        #pragma unroll
        for (int ks = 0; ks < 4; ks++) {
            const float* ar = ws + (mt * 16 + g) * WPITCH + ks * 8 + t4;
            float a0 = ar[0], a1 = ar[8 * WPITCH], a2 = ar[4], a3 = ar[8 * WPITCH + 4];
            #pragma unroll
            for (int nt = 0; nt < 2; nt++) {
                int nb = (nh * 2 + nt) * 8 + g;
                float b0 = Bt[nb * BPITCH + kk + ks * 8 + t4];
                float b1 = Bt[nb * BPITCH + kk + ks * 8 + 4 + t4];
                mma_tf32(c[nt], a0, a1, a2, a3, b0, b1);
            }
        }

        if (ch + NSTAGE - 1 < NCHUNK) {
            int st = (ch + NSTAGE - 1) & 3;
            int kn = (ch + NSTAGE - 1) * 32;
            #pragma unroll
            for (int i = 0; i < 2; i++) {
                int s = tid + 256 * i;
                int row = s >> 3, c4 = (s & 7) * 4;
                cp_async16(ws_base + (uint32_t)(st * GB_ROWS * WPITCH + row * WPITCH + c4) * 4,
                           W + (size_t)(rowbase + row) * L_DIM + kn + c4);
            }
        }
        cp_commit();   // one commit per iter (possibly empty) keeps wait counts aligned
    }

    // epilogue
    const int row0 = rowbase + mt * 16 + g;
    const float bv0 = bias[row0];
    const float bv1 = bias[row0 + 8];
    #pragma unroll
    for (int nt = 0; nt < 2; nt++) {
        int bb = (nh * 2 + nt) * 8 + 2 * t4;
        if (is_k) {
            float* o0 = g_kern + (size_t)bb * (H_DIM * K_DIM);
            o0[row0]                     = c[nt][0] + bv0;
            o0[row0 + H_DIM * K_DIM]     = c[nt][1] + bv0;   // bb+1
            o0[row0 + 8]                 = c[nt][2] + bv1;
            o0[row0 + 8 + H_DIM * K_DIM] = c[nt][3] + bv1;
        } else {
            float* o0 = g_glob + (size_t)bb * H_DIM;
            o0[row0]             = c[nt][0] + bv0;
            o0[row0 + H_DIM]     = c[nt][1] + bv0;
            o0[row0 + 8]         = c[nt][2] + bv1;
            o0[row0 + 8 + H_DIM] = c[nt][3] + bv1;
        }
    }
}

// ============================================================================
// Kernel B: tensor-core conv + enc + global -> tanh -> Ws -> exp  (R3 version)
// ============================================================================
__global__ void __launch_bounds__(128) score_kernel(
    const float* __restrict__ enc,   // (T,B,H)
    const float* __restrict__ prev,  // (T,B)
    const float* __restrict__ mask,  // (T,B)
    const float* __restrict__ Ws,    // (H)
    const float* __restrict__ bsp)   // (1)
{
    const int b    = blockIdx.y;
    const int t0   = blockIdx.x * T_BLK;
    const int tid  = threadIdx.x;
    const int wid  = tid >> 5;
    const int lane = tid & 31;
    const int gid  = lane >> 2;   // 0..7
    const int tig  = lane & 3;    // 0..3

    __shared__ float win_s[160];                       // prev_pad window
    __shared__ __align__(16) unsigned A_sm[128 * 20];  // bf16x2, pitch 20 u32
    __shared__ __align__(16) unsigned B_sm[256 * 20];
    __shared__ float part[T_BLK][4];
    __shared__ float red4[4];

    for (int i = tid; i < 160; i += 128) {
        int tg = t0 + i - (K_DIM - 1);
        win_s[i] = (tg >= 0 && tg < T_DIM) ? prev[(size_t)tg * B_DIM + b] : 0.f;
    }
    {
        const float2* kp = reinterpret_cast<const float2*>(g_kern + (size_t)b * H_DIM * K_DIM);
        #pragma unroll
        for (int i = tid; i < (H_DIM * K_DIM) / 2; i += 128) {
            float2 v = kp[i];
            int h = i >> 4, k2 = i & 15;
            B_sm[h * 20 + k2] = cvt_bf2(v.x, v.y);
        }
    }
    __syncthreads();

    {
        int r = tid;
        #pragma unroll
        for (int k2 = 0; k2 < 16; k2++)
            A_sm[r * 20 + k2] = cvt_bf2(win_s[r + 2 * k2], win_s[r + 2 * k2 + 1]);
    }

    const int hw0 = wid * 64;
    unsigned Bf[8][2][2];
    {
        uint32_t bbase = smem_u32(B_sm);
        #pragma unroll
        for (int j = 0; j < 8; j++)
            #pragma unroll
            for (int kt = 0; kt < 2; kt++) {
                uint32_t addr = bbase + (uint32_t)(hw0 + j * 8 + (lane & 7)) * 80
                              + kt * 32 + ((lane >> 3) & 1) * 16;
                ldsm_x2(Bf[j][kt][0], Bf[j][kt][1], addr);
            }
    }
    float2 gv2[8], ws2[8];
    #pragma unroll
    for (int j = 0; j < 8; j++) {
        int h0 = hw0 + j * 8 + 2 * tig;
        gv2[j] = *reinterpret_cast<const float2*>(g_glob + (size_t)b * H_DIM + h0);
        ws2[j] = *reinterpret_cast<const float2*>(Ws + h0);
    }
    __syncthreads();

    const uint32_t abase = smem_u32(A_sm);
    const uint32_t a_off = (uint32_t)(lane & 15) * 80 + (uint32_t)(lane >> 4) * 16;

    #pragma unroll 1
    for (int m = 0; m < 8; m++) {
        unsigned a0[4], a1[4];
        ldsm_x4(a0, abase + (uint32_t)m * 16 * 80 + a_off);        // k 0..15
        ldsm_x4(a1, abase + (uint32_t)m * 16 * 80 + a_off + 32);   // k 16..31

        const int ta = t0 + m * 16 + gid;
        const float* e_row0 = enc + ((size_t)ta * B_DIM + b) * H_DIM;
        const float* e_row1 = e_row0 + (size_t)8 * B_DIM * H_DIM;

        float sum0 = 0.f, sum1 = 0.f;
        #pragma unroll
        for (int jh = 0; jh < 2; jh++) {
            float c[4][4];
            #pragma unroll
            for (int j4 = 0; j4 < 4; j4++) {
                c[j4][0] = c[j4][1] = c[j4][2] = c[j4][3] = 0.f;
                mma_bf16(c[j4], a0, Bf[jh * 4 + j4][0]);
                mma_bf16(c[j4], a1, Bf[jh * 4 + j4][1]);
            }
            #pragma unroll
            for (int j4 = 0; j4 < 4; j4++) {
                int j = jh * 4 + j4;
                int h0 = hw0 + j * 8 + 2 * tig;
                float2 e0 = *reinterpret_cast<const float2*>(e_row0 + h0);
                float2 e1 = *reinterpret_cast<const float2*>(e_row1 + h0);
                sum0 += ws2[j].x * tanh_ap(c[j4][0] + e0.x + gv2[j].x)
                      + ws2[j].y * tanh_ap(c[j4][1] + e0.y + gv2[j].y);
                sum1 += ws2[j].x * tanh_ap(c[j4][2] + e1.x + gv2[j].x)
                      + ws2[j].y * tanh_ap(c[j4][3] + e1.y + gv2[j].y);
            }
        }
        sum0 += __shfl_xor_sync(0xFFFFFFFFu, sum0, 1);
        sum0 += __shfl_xor_sync(0xFFFFFFFFu, sum0, 2);
        sum1 += __shfl_xor_sync(0xFFFFFFFFu, sum1, 1);
        sum1 += __shfl_xor_sync(0xFFFFFFFFu, sum1, 2);
        if (tig == 0) {
            part[m * 16 + gid][wid]     = sum0;
            part[m * 16 + gid + 8][wid] = sum1;
        }
    }
    __syncthreads();

    const int t = t0 + tid;
    float s = part[tid][0] + part[tid][1] + part[tid][2] + part[tid][3] + bsp[0];
    float e = __expf(s + mask[(size_t)t * B_DIM + b]);
    g_exp[(size_t)t * B_DIM + b] = e;

    float v = e;
    v += __shfl_xor_sync(0xFFFFFFFFu, v, 16);
    v += __shfl_xor_sync(0xFFFFFFFFu, v, 8);
    v += __shfl_xor_sync(0xFFFFFFFFu, v, 4);
    v += __shfl_xor_sync(0xFFFFFFFFu, v, 2);
    v += __shfl_xor_sync(0xFFFFFFFFu, v, 1);
    if (lane == 0) red4[wid] = v;
    __syncthreads();
    if (tid == 0)
        g_part[(size_t)blockIdx.x * B_DIM + b] = red4[0] + red4[1] + red4[2] + red4[3];
}

// ============================================================================
// Kernel C: normalize  out[t,b] = g_exp[t,b] / sum_b
// ============================================================================
__global__ void __launch_bounds__(128) norm_kernel(float* __restrict__ out)
{
    __shared__ float inv_s;
    const int b = blockIdx.y;
    const int tid = threadIdx.x;

    if (tid < 32) {
        float v = g_part[(size_t)tid * B_DIM + b];
        v += __shfl_xor_sync(0xFFFFFFFFu, v, 16);
        v += __shfl_xor_sync(0xFFFFFFFFu, v, 8);
        v += __shfl_xor_sync(0xFFFFFFFFu, v, 4);
        v += __shfl_xor_sync(0xFFFFFFFFu, v, 2);
        v += __shfl_xor_sync(0xFFFFFFFFu, v, 1);
        if (tid == 0) inv_s = 1.0f / v;
    }
    __syncthreads();

    int t = blockIdx.x * 128 + tid;
    out[(size_t)t * B_DIM + b] = g_exp[(size_t)t * B_DIM + b] * inv_s;
}

// ============================================================================
extern "C" void kernel_launch(void* const* d_in, const int* in_sizes, int n_in,
                              void* d_out, int out_size)
{
    const float* enc  = (const float*)d_in[0];
    const float* mask = (const float*)d_in[1];
    const float* lm   = (const float*)d_in[2];
    const float* prev = (const float*)d_in[3];
    const float* Wk   = (const float*)d_in[4];
    const float* bk   = (const float*)d_in[5];
    const float* Wg   = (const float*)d_in[6];
    const float* bg   = (const float*)d_in[7];
    const float* Ws   = (const float*)d_in[8];
    const float* bs   = (const float*)d_in[9];
    float* out = (float*)d_out;

    static bool attr_set = false;
    if (!attr_set) {
        cudaFuncSetAttribute(gemm_tc_kernel,
                             cudaFuncAttributeMaxDynamicSharedMemorySize, GEMM_SMEM);
        attr_set = true;
    }

    // Wk (128 blocks) + Wg (4 blocks), pipelined tf32 tensor cores
    gemm_tc_kernel<<<(K_DIM * H_DIM) / GB_ROWS + H_DIM / GB_ROWS, 256, GEMM_SMEM>>>(
        Wk, bk, Wg, bg, lm);
    // tensor-core conv + tanh + score + exp + partial sums
    score_kernel<<<dim3(T_DIM / T_BLK, B_DIM), 128>>>(enc, prev, mask, Ws, bs);
    // normalize
    norm_kernel<<<dim3(T_DIM / 128, B_DIM), 128>>>(out);
}

// round 7
// speedup vs baseline: 1.8858x; 1.0679x over previous
#include <cuda_runtime.h>
#include <cstdint>

#define T_DIM 4096
#define B_DIM 32
#define H_DIM 256
#define L_DIM 512
#define K_DIM 32
#define T_BLK 128

// Scratch (allocation-free contract: __device__ globals)
__device__ __align__(16) float g_kern[B_DIM * H_DIM * K_DIM];   // [b][h*K+k] fp32
__device__ __align__(16) float g_glob[B_DIM * H_DIM];           // (B,H)
__device__ __align__(16) float g_exp[T_DIM * B_DIM];            // exp(score+mask)
__device__ __align__(16) float g_part[(T_DIM / T_BLK) * B_DIM]; // partial exp sums

// ---- helpers ----
__device__ __forceinline__ float tanh_ap(float x) {
    float y; asm("tanh.approx.f32 %0, %1;" : "=f"(y) : "f"(x)); return y;
}
__device__ __forceinline__ unsigned cvt_bf2(float lo, float hi) {
    unsigned d; asm("cvt.rn.bf16x2.f32 %0, %1, %2;" : "=r"(d) : "f"(hi), "f"(lo)); return d;
}
__device__ __forceinline__ uint32_t smem_u32(const void* p) {
    return (uint32_t)__cvta_generic_to_shared(p);
}
__device__ __forceinline__ void cp_async16(uint32_t dst, const void* src) {
    asm volatile("cp.async.cg.shared.global [%0], [%1], 16;" :: "r"(dst), "l"(src));
}
__device__ __forceinline__ void cp_commit() {
    asm volatile("cp.async.commit_group;");
}
__device__ __forceinline__ void ldsm_x4(unsigned r[4], uint32_t addr) {
    asm volatile("ldmatrix.sync.aligned.m8n8.x4.shared.b16 {%0,%1,%2,%3}, [%4];"
        : "=r"(r[0]), "=r"(r[1]), "=r"(r[2]), "=r"(r[3]) : "r"(addr));
}
__device__ __forceinline__ void ldsm_x2(unsigned& r0, unsigned& r1, uint32_t addr) {
    asm volatile("ldmatrix.sync.aligned.m8n8.x2.shared.b16 {%0,%1}, [%2];"
        : "=r"(r0), "=r"(r1) : "r"(addr));
}
__device__ __forceinline__ void mma_bf16(float c[4], const unsigned a[4], const unsigned b[2]) {
    asm volatile("mma.sync.aligned.m16n8k16.row.col.f32.bf16.bf16.f32 "
        "{%0,%1,%2,%3}, {%4,%5,%6,%7}, {%8,%9}, {%0,%1,%2,%3};"
        : "+f"(c[0]), "+f"(c[1]), "+f"(c[2]), "+f"(c[3])
        : "r"(a[0]), "r"(a[1]), "r"(a[2]), "r"(a[3]), "r"(b[0]), "r"(b[1]));
}
// raw fp32 operands (hardware truncates to tf32)
__device__ __forceinline__ void mma_tf32(float c[4],
    float a0, float a1, float a2, float a3, float b0, float b1) {
    asm volatile("mma.sync.aligned.m16n8k8.row.col.f32.tf32.tf32.f32 "
        "{%0,%1,%2,%3}, {%4,%5,%6,%7}, {%8,%9}, {%0,%1,%2,%3};"
        : "+f"(c[0]), "+f"(c[1]), "+f"(c[2]), "+f"(c[3])
        : "r"(__float_as_uint(a0)), "r"(__float_as_uint(a1)),
          "r"(__float_as_uint(a2)), "r"(__float_as_uint(a3)),
          "r"(__float_as_uint(b0)), "r"(__float_as_uint(b1)));
}

// ============================================================================
// Kernel A: tf32 MMA GEMM with cp.async 8-stage pipeline.
// ============================================================================
#define GB_ROWS 64
#define WPITCH  36
#define BPITCH  516
#define NSTAGE  8
#define NCHUNK  (L_DIM / 32)          // 16
#define GEMM_SMEM ((B_DIM * BPITCH + NSTAGE * GB_ROWS * WPITCH) * 4)

__global__ void __launch_bounds__(256) gemm_tc_kernel(
    const float* __restrict__ Wk, const float* __restrict__ bk,
    const float* __restrict__ Wg, const float* __restrict__ bg,
    const float* __restrict__ lm)
{
    extern __shared__ float smem[];
    float* Bt  = smem;                       // [32][516]
    float* Wst = smem + B_DIM * BPITCH;      // [8][64][36]

    const int tid  = threadIdx.x;
    const int warp = tid >> 5;
    const int lane = tid & 31;
    const int g    = lane >> 2;
    const int t4   = lane & 3;
    const int mt   = warp >> 1;
    const int nh   = warp & 1;

    const bool is_k = (blockIdx.x < (K_DIM * H_DIM) / GB_ROWS);
    const float* W    = is_k ? Wk : Wg;
    const float* bias = is_k ? bk : bg;
    const int rowbase = (is_k ? blockIdx.x : (blockIdx.x - (K_DIM * H_DIM) / GB_ROWS)) * GB_ROWS;

    const uint32_t bt_base = smem_u32(Bt);
    const uint32_t ws_base = smem_u32(Wst);

    // group 0: lm -> Bt[b][k]
    #pragma unroll
    for (int i = 0; i < 16; i++) {
        int s = tid + 256 * i;
        int bb = s >> 7, k4 = (s & 127) * 4;
        cp_async16(bt_base + (uint32_t)(bb * BPITCH + k4) * 4,
                   lm + (size_t)bb * L_DIM + k4);
    }
    cp_commit();

    // prologue: W chunks 0..NSTAGE-2
    #pragma unroll
    for (int st = 0; st < NSTAGE - 1; st++) {
        #pragma unroll
        for (int i = 0; i < 2; i++) {
            int s = tid + 256 * i;
            int row = s >> 3, c4 = (s & 7) * 4;
            cp_async16(ws_base + (uint32_t)(st * GB_ROWS * WPITCH + row * WPITCH + c4) * 4,
                       W + (size_t)(rowbase + row) * L_DIM + st * 32 + c4);
        }
        cp_commit();
    }

    float c[2][4];
    #pragma unroll
    for (int nt = 0; nt < 2; nt++)
        #pragma unroll
        for (int j = 0; j < 4; j++) c[nt][j] = 0.f;

    #pragma unroll 1
    for (int ch = 0; ch < NCHUNK; ch++) {
        asm volatile("cp.async.wait_group 6;");
        __syncthreads();

        const float* ws = Wst + (ch & (NSTAGE - 1)) * GB_ROWS * WPITCH;
        const int kk = ch * 32;
        #pragma unroll
        for (int ks = 0; ks < 4; ks++) {
            const float* ar = ws + (mt * 16 + g) * WPITCH + ks * 8 + t4;
            float a0 = ar[0], a1 = ar[8 * WPITCH], a2 = ar[4], a3 = ar[8 * WPITCH + 4];
            #pragma unroll
            for (int nt = 0; nt < 2; nt++) {
                int nb = (nh * 2 + nt) * 8 + g;
                float b0 = Bt[nb * BPITCH + kk + ks * 8 + t4];
                float b1 = Bt[nb * BPITCH + kk + ks * 8 + 4 + t4];
                mma_tf32(c[nt], a0, a1, a2, a3, b0, b1);
            }
        }

        if (ch + NSTAGE - 1 < NCHUNK) {
            int st = (ch + NSTAGE - 1) & (NSTAGE - 1);
            int kn = (ch + NSTAGE - 1) * 32;
            #pragma unroll
            for (int i = 0; i < 2; i++) {
                int s = tid + 256 * i;
                int row = s >> 3, c4 = (s & 7) * 4;
                cp_async16(ws_base + (uint32_t)(st * GB_ROWS * WPITCH + row * WPITCH + c4) * 4,
                           W + (size_t)(rowbase + row) * L_DIM + kn + c4);
            }
        }
        cp_commit();
    }

    const int row0 = rowbase + mt * 16 + g;
    const float bv0 = bias[row0];
    const float bv1 = bias[row0 + 8];
    #pragma unroll
    for (int nt = 0; nt < 2; nt++) {
        int bb = (nh * 2 + nt) * 8 + 2 * t4;
        if (is_k) {
            float* o0 = g_kern + (size_t)bb * (H_DIM * K_DIM);
            o0[row0]                     = c[nt][0] + bv0;
            o0[row0 + H_DIM * K_DIM]     = c[nt][1] + bv0;
            o0[row0 + 8]                 = c[nt][2] + bv1;
            o0[row0 + 8 + H_DIM * K_DIM] = c[nt][3] + bv1;
        } else {
            float* o0 = g_glob + (size_t)bb * H_DIM;
            o0[row0]             = c[nt][0] + bv0;
            o0[row0 + H_DIM]     = c[nt][1] + bv0;
            o0[row0 + 8]         = c[nt][2] + bv1;
            o0[row0 + 8 + H_DIM] = c[nt][3] + bv1;
        }
    }
}

// ============================================================================
// Kernel B: tensor-core conv + enc + global -> tanh -> Ws -> exp
// enc staged through smem (cp.async double buffer, 16 rows x 1KB per m-iter)
// ============================================================================
#define EPITCH 260                      // floats per staged enc row
#define SC_SMEM ((2 * 16 * EPITCH + 2560 + 5120 + 160 + 512 + 4 + 4) * 4)

__global__ void __launch_bounds__(128) score_kernel(
    const float* __restrict__ enc,   // (T,B,H)
    const float* __restrict__ prev,  // (T,B)
    const float* __restrict__ mask,  // (T,B)
    const float* __restrict__ Ws,    // (H)
    const float* __restrict__ bsp)   // (1)
{
    extern __shared__ float dsm[];
    float*    E_sm  = dsm;                                      // [2][16][260]
    unsigned* A_sm  = reinterpret_cast<unsigned*>(dsm + 2 * 16 * EPITCH);
    unsigned* B_sm  = A_sm + 2560;                              // 256*20
    float*    win_s = reinterpret_cast<float*>(B_sm + 5120);    // 160
    float*    part  = win_s + 160;                              // [128][4]
    float*    red4  = part + 512;                               // 4

    const int b    = blockIdx.y;
    const int t0   = blockIdx.x * T_BLK;
    const int tid  = threadIdx.x;
    const int wid  = tid >> 5;
    const int lane = tid & 31;
    const int gid  = lane >> 2;
    const int tig  = lane & 3;

    const uint32_t e_base = smem_u32(E_sm);

    // ---- stage enc m=0 immediately (group 0) ----
    #pragma unroll
    for (int i = 0; i < 8; i++) {
        int s = tid + 128 * i;
        int r = s >> 6, c16 = (s & 63) * 4;     // row 0..15, col float4
        cp_async16(e_base + (uint32_t)(r * EPITCH + c16) * 4,
                   enc + ((size_t)(t0 + r) * B_DIM + b) * H_DIM + c16);
    }
    cp_commit();

    // ---- fill prev window + B (kern -> bf16) ----
    for (int i = tid; i < 160; i += 128) {
        int tg = t0 + i - (K_DIM - 1);
        win_s[i] = (tg >= 0 && tg < T_DIM) ? prev[(size_t)tg * B_DIM + b] : 0.f;
    }
    {
        const float2* kp = reinterpret_cast<const float2*>(g_kern + (size_t)b * H_DIM * K_DIM);
        #pragma unroll
        for (int i = tid; i < (H_DIM * K_DIM) / 2; i += 128) {
            float2 v = kp[i];
            int h = i >> 4, k2 = i & 15;
            B_sm[h * 20 + k2] = cvt_bf2(v.x, v.y);
        }
    }
    __syncthreads();

    // ---- fill A (Hankel windows, bf16) ----
    {
        int r = tid;
        #pragma unroll
        for (int k2 = 0; k2 < 16; k2++)
            A_sm[r * 20 + k2] = cvt_bf2(win_s[r + 2 * k2], win_s[r + 2 * k2 + 1]);
    }

    // ---- B fragments + per-lane epilogue constants ----
    const int hw0 = wid * 64;
    unsigned Bf[8][2][2];
    {
        uint32_t bbase = smem_u32(B_sm);
        #pragma unroll
        for (int j = 0; j < 8; j++)
            #pragma unroll
            for (int kt = 0; kt < 2; kt++) {
                uint32_t addr = bbase + (uint32_t)(hw0 + j * 8 + (lane & 7)) * 80
                              + kt * 32 + ((lane >> 3) & 1) * 16;
                ldsm_x2(Bf[j][kt][0], Bf[j][kt][1], addr);
            }
    }
    float2 gv2[8], ws2[8];
    #pragma unroll
    for (int j = 0; j < 8; j++) {
        int h0 = hw0 + j * 8 + 2 * tig;
        gv2[j] = *reinterpret_cast<const float2*>(g_glob + (size_t)b * H_DIM + h0);
        ws2[j] = *reinterpret_cast<const float2*>(Ws + h0);
    }
    __syncthreads();

    const uint32_t abase = smem_u32(A_sm);
    const uint32_t a_off = (uint32_t)(lane & 15) * 80 + (uint32_t)(lane >> 4) * 16;

    #pragma unroll 1
    for (int m = 0; m < 8; m++) {
        // wait for this m's enc tile; sync also fences previous compute
        asm volatile("cp.async.wait_group 0;");
        __syncthreads();

        // prefetch next tile into the other buffer (overlaps with compute)
        if (m + 1 < 8) {
            uint32_t dst = e_base + (uint32_t)(((m + 1) & 1) * 16 * EPITCH) * 4;
            #pragma unroll
            for (int i = 0; i < 8; i++) {
                int s = tid + 128 * i;
                int r = s >> 6, c16 = (s & 63) * 4;
                cp_async16(dst + (uint32_t)(r * EPITCH + c16) * 4,
                           enc + ((size_t)(t0 + (m + 1) * 16 + r) * B_DIM + b) * H_DIM + c16);
            }
        }
        cp_commit();

        unsigned a0[4], a1[4];
        ldsm_x4(a0, abase + (uint32_t)m * 16 * 80 + a_off);
        ldsm_x4(a1, abase + (uint32_t)m * 16 * 80 + a_off + 32);

        const float* E = E_sm + (m & 1) * 16 * EPITCH;

        float sum0 = 0.f, sum1 = 0.f;
        #pragma unroll
        for (int jh = 0; jh < 2; jh++) {
            float c[4][4];
            #pragma unroll
            for (int j4 = 0; j4 < 4; j4++) {
                c[j4][0] = c[j4][1] = c[j4][2] = c[j4][3] = 0.f;
                mma_bf16(c[j4], a0, Bf[jh * 4 + j4][0]);
                mma_bf16(c[j4], a1, Bf[jh * 4 + j4][1]);
            }
            #pragma unroll
            for (int j4 = 0; j4 < 4; j4++) {
                int j = jh * 4 + j4;
                int h0 = hw0 + j * 8 + 2 * tig;
                float2 e0 = *reinterpret_cast<const float2*>(E + gid * EPITCH + h0);
                float2 e1 = *reinterpret_cast<const float2*>(E + (gid + 8) * EPITCH + h0);
                sum0 += ws2[j].x * tanh_ap(c[j4][0] + e0.x + gv2[j].x)
                      + ws2[j].y * tanh_ap(c[j4][1] + e0.y + gv2[j].y);
                sum1 += ws2[j].x * tanh_ap(c[j4][2] + e1.x + gv2[j].x)
                      + ws2[j].y * tanh_ap(c[j4][3] + e1.y + gv2[j].y);
            }
        }
        sum0 += __shfl_xor_sync(0xFFFFFFFFu, sum0, 1);
        sum0 += __shfl_xor_sync(0xFFFFFFFFu, sum0, 2);
        sum1 += __shfl_xor_sync(0xFFFFFFFFu, sum1, 1);
        sum1 += __shfl_xor_sync(0xFFFFFFFFu, sum1, 2);
        if (tig == 0) {
            part[(m * 16 + gid) * 4 + wid]     = sum0;
            part[(m * 16 + gid + 8) * 4 + wid] = sum1;
        }
    }
    __syncthreads();

    const int t = t0 + tid;
    float s = part[tid * 4 + 0] + part[tid * 4 + 1] + part[tid * 4 + 2] + part[tid * 4 + 3]
            + bsp[0];
    float e = __expf(s + mask[(size_t)t * B_DIM + b]);
    g_exp[(size_t)t * B_DIM + b] = e;

    float v = e;
    v += __shfl_xor_sync(0xFFFFFFFFu, v, 16);
    v += __shfl_xor_sync(0xFFFFFFFFu, v, 8);
    v += __shfl_xor_sync(0xFFFFFFFFu, v, 4);
    v += __shfl_xor_sync(0xFFFFFFFFu, v, 2);
    v += __shfl_xor_sync(0xFFFFFFFFu, v, 1);
    if (lane == 0) red4[wid] = v;
    __syncthreads();
    if (tid == 0)
        g_part[(size_t)blockIdx.x * B_DIM + b] = red4[0] + red4[1] + red4[2] + red4[3];
}

// ============================================================================
// Kernel C: normalize
// ============================================================================
__global__ void __launch_bounds__(128) norm_kernel(float* __restrict__ out)
{
    __shared__ float inv_s;
    const int b = blockIdx.y;
    const int tid = threadIdx.x;

    if (tid < 32) {
        float v = g_part[(size_t)tid * B_DIM + b];
        v += __shfl_xor_sync(0xFFFFFFFFu, v, 16);
        v += __shfl_xor_sync(0xFFFFFFFFu, v, 8);
        v += __shfl_xor_sync(0xFFFFFFFFu, v, 4);
        v += __shfl_xor_sync(0xFFFFFFFFu, v, 2);
        v += __shfl_xor_sync(0xFFFFFFFFu, v, 1);
        if (tid == 0) inv_s = 1.0f / v;
    }
    __syncthreads();

    int t = blockIdx.x * 128 + tid;
    out[(size_t)t * B_DIM + b] = g_exp[(size_t)t * B_DIM + b] * inv_s;
}

// ============================================================================
extern "C" void kernel_launch(void* const* d_in, const int* in_sizes, int n_in,
                              void* d_out, int out_size)
{
    const float* enc  = (const float*)d_in[0];
    const float* mask = (const float*)d_in[1];
    const float* lm   = (const float*)d_in[2];
    const float* prev = (const float*)d_in[3];
    const float* Wk   = (const float*)d_in[4];
    const float* bk   = (const float*)d_in[5];
    const float* Wg   = (const float*)d_in[6];
    const float* bg   = (const float*)d_in[7];
    const float* Ws   = (const float*)d_in[8];
    const float* bs   = (const float*)d_in[9];
    float* out = (float*)d_out;

    static bool attr_set = false;
    if (!attr_set) {
        cudaFuncSetAttribute(gemm_tc_kernel,
                             cudaFuncAttributeMaxDynamicSharedMemorySize, GEMM_SMEM);
        cudaFuncSetAttribute(score_kernel,
                             cudaFuncAttributeMaxDynamicSharedMemorySize, SC_SMEM);
        attr_set = true;
    }

    gemm_tc_kernel<<<(K_DIM * H_DIM) / GB_ROWS + H_DIM / GB_ROWS, 256, GEMM_SMEM>>>(
        Wk, bk, Wg, bg, lm);
    score_kernel<<<dim3(T_DIM / T_BLK, B_DIM), 128, SC_SMEM>>>(enc, prev, mask, Ws, bs);
    norm_kernel<<<dim3(T_DIM / 128, B_DIM), 128>>>(out);
}